// round 12
// baseline (speedup 1.0000x reference)
#include <cuda_runtime.h>
#include <cstdint>

#define T_DIM 1024
#define B_DIM 256
#define I_DIM 128
#define H_DIM 256

// ---------- packed fp32x2 helpers (each lane = independent scalar RN FMA) ----
static __device__ __forceinline__ unsigned long long ffma2(
    unsigned long long a, unsigned long long b, unsigned long long c) {
    unsigned long long d;
    asm("fma.rn.f32x2 %0, %1, %2, %3;" : "=l"(d) : "l"(a), "l"(b), "l"(c));
    return d;
}
static __device__ __forceinline__ unsigned long long packdup(float w) {
    unsigned long long d;
    asm("mov.b64 %0, {%1, %1};" : "=l"(d) : "f"(w));
    return d;
}
static __device__ __forceinline__ float lof(unsigned long long v) {
    return __uint_as_float((unsigned int)(v & 0xffffffffULL));
}
static __device__ __forceinline__ float hif(unsigned long long v) {
    return __uint_as_float((unsigned int)(v >> 32));
}

// ---------- reference-matched tanh: MLIR clamp, FMA-contracted rational ------
static __device__ __forceinline__ float ref_tanh(float x) {
    const float kClamp = 7.99881172180175781f;
    float xc = fminf(fmaxf(x, -kClamp), kClamp);
    float x2 = __fmul_rn(xc, xc);
    float p;
    p = __fmaf_rn(x2, -2.76076847742355e-16f, 2.00018790482477e-13f);
    p = __fmaf_rn(x2, p, -8.60467152213735e-11f);
    p = __fmaf_rn(x2, p,  5.12229709037114e-08f);
    p = __fmaf_rn(x2, p,  1.48572235717979e-05f);
    p = __fmaf_rn(x2, p,  6.37261928875436e-04f);
    p = __fmaf_rn(x2, p,  4.89352455891786e-03f);
    p = __fmul_rn(xc, p);
    float q;
    q = __fmaf_rn(x2, 1.19825839466702e-06f, 1.18534705686654e-04f);
    q = __fmaf_rn(x2, q, 2.26843463243900e-03f);
    q = __fmaf_rn(x2, q, 4.89352518554385e-03f);
    float r = __fdiv_rn(p, q);
    return (fabsf(x) < 0.0004f) ? x : r;
}

// Transposed Wh scratch: g_WhT[k][j] = Wh[j][k]
__device__ float g_WhT[H_DIM * H_DIM];

__global__ void __launch_bounds__(256) transpose_wh_kernel(const float* __restrict__ Wh) {
    g_WhT[threadIdx.x * H_DIM + blockIdx.x] = Wh[blockIdx.x * H_DIM + threadIdx.x];
}

// ============================================================
// Kernel 1: xproj, f32x2 over batch-row pairs. Per lane: flat ascending-i
// single-acc FMA chain + fp32 bias add — bitwise identical to reference.
// grid (1024, 16), 256 thr; thread = j, 16 rows (8 pairs).
// X staged pair-transposed: xsp[p][i] = (X[b0+2p][t][i], X[b0+2p+1][t][i]).
// ============================================================
__global__ void __launch_bounds__(256) xproj_kernel(
    const float* __restrict__ X, const float* __restrict__ Wi,
    const float* __restrict__ bh, float* __restrict__ out)
{
    __shared__ __align__(16) float2 xsp[8][I_DIM];

    const int t   = blockIdx.x;
    const int b0  = blockIdx.y * 16;
    const int tid = threadIdx.x;
    const int j   = tid;

    // stage X: 2 float4 per thread, scattered into pair-transposed layout
    const float4* X4 = reinterpret_cast<const float4*>(X);
#pragma unroll
    for (int v = 0; v < 2; v++) {
        int lin = tid + v * 256, bb = lin >> 5, i4 = lin & 31;
        float4 val = X4[((size_t)(b0 + bb) * T_DIM + t) * 32 + i4];
        int p = bb >> 1;
        if ((bb & 1) == 0) {
            xsp[p][i4 * 4 + 0].x = val.x; xsp[p][i4 * 4 + 1].x = val.y;
            xsp[p][i4 * 4 + 2].x = val.z; xsp[p][i4 * 4 + 3].x = val.w;
        } else {
            xsp[p][i4 * 4 + 0].y = val.x; xsp[p][i4 * 4 + 1].y = val.y;
            xsp[p][i4 * 4 + 2].y = val.z; xsp[p][i4 * 4 + 3].y = val.w;
        }
    }
    __syncthreads();

    unsigned long long acc[8];
#pragma unroll
    for (int p = 0; p < 8; p++) acc[p] = 0ULL;

    const float4* wrow = reinterpret_cast<const float4*>(Wi + (size_t)j * I_DIM);

#pragma unroll 4
    for (int ig = 0; ig < 32; ig++) {       // 4 ascending i per group
        float4 w = wrow[ig];
        unsigned long long wx = packdup(w.x), wy = packdup(w.y);
        unsigned long long wz = packdup(w.z), ww = packdup(w.w);
#pragma unroll
        for (int p = 0; p < 8; p++) {
            ulonglong2 A = *reinterpret_cast<const ulonglong2*>(&xsp[p][ig * 4]);
            ulonglong2 Bv = *reinterpret_cast<const ulonglong2*>(&xsp[p][ig * 4 + 2]);
            acc[p] = ffma2(wx, A.x,  acc[p]);
            acc[p] = ffma2(wy, A.y,  acc[p]);
            acc[p] = ffma2(wz, Bv.x, acc[p]);
            acc[p] = ffma2(ww, Bv.y, acc[p]);
        }
    }

    const float bhj = bh[j];
    size_t base = ((size_t)t * B_DIM + b0) * H_DIM + j;
#pragma unroll
    for (int p = 0; p < 8; p++) {
        out[base + (size_t)(2 * p) * H_DIM]     = __fadd_rn(lof(acc[p]), bhj);
        out[base + (size_t)(2 * p + 1) * H_DIM] = __fadd_rn(hif(acc[p]), bhj);
    }
}

// ============================================================
// Kernel 2: recurrence. 128 CTAs x 256 thr; CTA owns rows (2*blk, 2*blk+1);
// thread = column j, both rows packed in ONE f32x2 chain (lane lo = row0,
// lane hi = row1) — each lane is the exact flat ascending-k scalar chain.
// Wh[j][k]: k<80 pre-packed dup in registers; k>=80 scalar in smem [k][j].
// h ping-pong: hbuf[buf][k] = (h_row0[k], h_row1[k]) — the packed operand.
// ============================================================
#define WREG 80
#define WSMK (H_DIM - WREG)     // 176

__global__ void __launch_bounds__(256, 1) rnn_rec_kernel(float* __restrict__ out) {
    extern __shared__ float wsm[];                     // [WSMK][256]
    __shared__ __align__(16) float2 hbuf[2][H_DIM];

    const int j   = threadIdx.x;
    const int b0  = blockIdx.x * 2;

    unsigned long long wp[WREG];
#pragma unroll
    for (int k = 0; k < WREG; k++) wp[k] = packdup(g_WhT[k * H_DIM + j]);
    for (int k = WREG; k < H_DIM; k++) wsm[(k - WREG) * H_DIM + j] = g_WhT[k * H_DIM + j];

    hbuf[0][j] = make_float2(0.0f, 0.0f);
    __syncthreads();

    int cur = 0;
    size_t base = (size_t)b0 * H_DIM + j;

    for (int t = 0; t < T_DIM; t++) {
        float xp0 = out[base];
        float xp1 = out[base + H_DIM];

        unsigned long long acc = 0ULL;

        // k in [0, WREG): packed w in regs; ulonglong2 h loads (2 k's)
#pragma unroll
        for (int k = 0; k < WREG; k += 2) {
            ulonglong2 hv = *reinterpret_cast<const ulonglong2*>(&hbuf[cur][k]);
            acc = ffma2(wp[k],     hv.x, acc);
            acc = ffma2(wp[k + 1], hv.y, acc);
        }
        // k in [WREG, 256): scalar w from smem (coalesced [k][j]), pack, FMA2
#pragma unroll 8
        for (int k = WREG; k < H_DIM; k += 2) {
            ulonglong2 hv = *reinterpret_cast<const ulonglong2*>(&hbuf[cur][k]);
            float w0 = wsm[(k - WREG) * H_DIM + j];
            float w1 = wsm[(k - WREG + 1) * H_DIM + j];
            acc = ffma2(packdup(w0), hv.x, acc);
            acc = ffma2(packdup(w1), hv.y, acc);
        }

        float hn0 = ref_tanh(__fadd_rn(xp0, lof(acc)));
        float hn1 = ref_tanh(__fadd_rn(xp1, hif(acc)));

        int nxt = cur ^ 1;
        hbuf[nxt][j] = make_float2(hn0, hn1);
        out[base]         = hn0;
        out[base + H_DIM] = hn1;
        __syncthreads();
        cur = nxt;
        base += (size_t)B_DIM * H_DIM;
    }
}

// ============================================================
extern "C" void kernel_launch(void* const* d_in, const int* in_sizes, int n_in,
                              void* d_out, int out_size) {
    const float* X  = nullptr; const float* Wi = nullptr;
    const float* Wh = nullptr; const float* bh = nullptr;
    for (int i = 0; i < n_in; i++) {
        switch (in_sizes[i]) {
            case B_DIM * T_DIM * I_DIM: X  = (const float*)d_in[i]; break;
            case H_DIM * I_DIM:         Wi = (const float*)d_in[i]; break;
            case H_DIM * H_DIM:         Wh = (const float*)d_in[i]; break;
            case H_DIM:                 bh = (const float*)d_in[i]; break;
            default: break;
        }
    }
    float* out = (float*)d_out;

    const int rec_smem = WSMK * H_DIM * (int)sizeof(float);   // 180224 B
    cudaFuncSetAttribute(rnn_rec_kernel,
                         cudaFuncAttributeMaxDynamicSharedMemorySize, rec_smem);

    transpose_wh_kernel<<<H_DIM, H_DIM>>>(Wh);
    xproj_kernel<<<dim3(T_DIM, B_DIM / 16), 256>>>(X, Wi, bh, out);
    rnn_rec_kernel<<<B_DIM / 2, 256, rec_smem>>>(out);
}